// round 17
// baseline (speedup 1.0000x reference)
#include <cuda_runtime.h>
#include <cuda_bf16.h>

// -----------------------------------------------------------------------------
// FrustumSegmentationNet — collapsed exact-math, ONE kernel (R14 structure),
// fast-path prep: one load round AFTER the barrier, no smem round-trip.
//
// R0 proof: FPS argmin always selects index 0 -> all groups identical ->
// axis-0 batchnorms collapse feats to the constant fc = bd3 + relu(be5)@Wd3^T.
// Output = per-pixel 6->80 linear with Kinv folded into per-channel (A,B,C)
// + folded bias; zero outside the box.
//
// R17 = R14 with the fast path reading bd3 directly into the reduction
// (concurrently with Ws bias-row + lane0 coef-row/bs loads) AFTER
// __syncthreads_or. Nothing besides be5 precedes the barrier (R12/R16 both
// showed early batching inflates live ranges and regresses). Fast-path
// barriers 4 -> 2, dependent LDG rounds 3 -> 2. Fallback path R14-verbatim.
// Pixel body / grid / __launch_bounds__(256,5): R14 verbatim.
// -----------------------------------------------------------------------------

#define HWPIX  65536
#define NCH    80

typedef unsigned long long u64;

__device__ __forceinline__ u64 pk2(float x) {
    u64 r; asm("mov.b64 %0, {%1, %1};" : "=l"(r) : "f"(x)); return r;
}
__device__ __forceinline__ u64 pair2(float lo, float hi) {
    u64 r; asm("mov.b64 %0, {%1, %2};" : "=l"(r) : "f"(lo), "f"(hi)); return r;
}
__device__ __forceinline__ u64 fma2(u64 a, u64 b, u64 c) {
    u64 d; asm("fma.rn.f32x2 %0, %1, %2, %3;" : "=l"(d) : "l"(a), "l"(b), "l"(c));
    return d;
}
__device__ __forceinline__ float warp_sum(float s) {
    #pragma unroll
    for (int off = 16; off > 0; off >>= 1)
        s += __shfl_down_sync(0xFFFFFFFFu, s, off);
    return s;
}

__global__ __launch_bounds__(256, 5)
void frustum_all_kernel(const float* __restrict__ rgb,    // (H,W,3)
                        const float* __restrict__ depth,  // (H,W)
                        const float* __restrict__ intr,   // (3,3)
                        const int*   __restrict__ box,    // (5)
                        const float* __restrict__ be5,    // (256)
                        const float* __restrict__ Wd3,    // (128,256)
                        const float* __restrict__ bd3,    // (128)
                        const float* __restrict__ Ws,     // (80,134)
                        const float* __restrict__ bs,     // (80)
                        float* __restrict__ out)          // (80,H,W)
{
    // blob first (LDS.128-accessed -> 16B aligned):
    // per channel: [A,A, B,B, C,C, w3,w3, w4,w4, w5,w5, bias,bias, 0,0]
    __shared__ __align__(16) float sP[8 * 16];
    __shared__ __align__(16) float sfc[128];   // fallback only
    __shared__ __align__(16) float sbe[256];   // fallback only
    __shared__ __align__(16) float sK[12];
    __shared__ __align__(16) float soff[4];
    __shared__ __align__(16) int   sbox[4];

    const int t     = threadIdx.x;
    const int warp  = t >> 5;
    const int lane  = t & 31;
    const int blk   = blockIdx.x;
    const int cbase = (blk >> 6) * 8;      // 64 blocks per channel group
    const int c     = cbase + warp;        // this warp's channel

    // ---- ONLY be5 (+ t0 scalars) before the barrier ----
    float bev = fmaxf(be5[t], 0.0f);
    sbe[t] = bev;
    if (t == 0) {
        float a = intr[0], b = intr[1], cc = intr[2];
        float d = intr[3], e = intr[4], f = intr[5];
        float gg = intr[6], h = intr[7], i9 = intr[8];
        float det = a * (e * i9 - f * h) - b * (d * i9 - f * gg) + cc * (d * h - e * gg);
        float inv = 1.0f / det;
        sK[0] = (e * i9 - f * h) * inv;  sK[1] = (cc * h - b * i9) * inv;  sK[2] = (b * f - cc * e) * inv;
        sK[3] = (f * gg - d * i9) * inv; sK[4] = (a * i9 - cc * gg) * inv; sK[5] = (cc * d - a * f) * inv;
        sK[6] = (d * h - e * gg) * inv;  sK[7] = (b * gg - a * h) * inv;   sK[8] = (a * e - b * d) * inv;
        int b0 = box[0], b1 = box[1], b2 = box[2], b3 = box[3];
        sbox[0] = b0; sbox[1] = b1; sbox[2] = b2; sbox[3] = b3;
        soff[0] = 0.5f - (float)b1;    // u offset (col)
        soff[1] = 0.5f - (float)b0;    // v offset (row)
    }

    const int any_pos = __syncthreads_or(bev > 0.0f);

    // ---- fc values: fast path reads bd3 straight into registers ----
    float v0, v1, v2, v3;
    if (!any_pos) {
        v0 = bd3[lane];      v1 = bd3[lane + 32];
        v2 = bd3[lane + 64]; v3 = bd3[lane + 96];
    } else {
        // general fallback: fc[j] = bd3[j] + relu(be5) . Wd3[j,:]
        #pragma unroll
        for (int bb = 0; bb < 4; bb++) {
            int j0 = warp * 16 + bb * 4;
            const float4* r0 = reinterpret_cast<const float4*>(Wd3 + (j0 + 0) * 256);
            const float4* r1 = reinterpret_cast<const float4*>(Wd3 + (j0 + 1) * 256);
            const float4* r2 = reinterpret_cast<const float4*>(Wd3 + (j0 + 2) * 256);
            const float4* r3 = reinterpret_cast<const float4*>(Wd3 + (j0 + 3) * 256);
            float4 a0 = r0[lane], b0v = r0[lane + 32];
            float4 a1 = r1[lane], b1v = r1[lane + 32];
            float4 a2 = r2[lane], b2v = r2[lane + 32];
            float4 a3 = r3[lane], b3v = r3[lane + 32];
            int k0 = 4 * lane, k1 = 128 + 4 * lane;
            float e0 = sbe[k0], e1 = sbe[k0+1], e2 = sbe[k0+2], e3 = sbe[k0+3];
            float f0 = sbe[k1], f1 = sbe[k1+1], f2 = sbe[k1+2], f3 = sbe[k1+3];
            float s0 = a0.x*e0 + a0.y*e1 + a0.z*e2 + a0.w*e3 + b0v.x*f0 + b0v.y*f1 + b0v.z*f2 + b0v.w*f3;
            float s1 = a1.x*e0 + a1.y*e1 + a1.z*e2 + a1.w*e3 + b1v.x*f0 + b1v.y*f1 + b1v.z*f2 + b1v.w*f3;
            float s2 = a2.x*e0 + a2.y*e1 + a2.z*e2 + a2.w*e3 + b2v.x*f0 + b2v.y*f1 + b2v.z*f2 + b2v.w*f3;
            float s3 = a3.x*e0 + a3.y*e1 + a3.z*e2 + a3.w*e3 + b3v.x*f0 + b3v.y*f1 + b3v.z*f2 + b3v.w*f3;
            s0 = warp_sum(s0); s1 = warp_sum(s1); s2 = warp_sum(s2); s3 = warp_sum(s3);
            if (lane == 0) {
                sfc[j0 + 0] = bd3[j0 + 0] + s0;
                sfc[j0 + 1] = bd3[j0 + 1] + s1;
                sfc[j0 + 2] = bd3[j0 + 2] + s2;
                sfc[j0 + 3] = bd3[j0 + 3] + s3;
            }
        }
        __syncthreads();
        v0 = sfc[lane]; v1 = sfc[lane + 32];
        v2 = sfc[lane + 64]; v3 = sfc[lane + 96];
    }

    // ---- one concurrent round: Ws bias row + lane0 coef row + bs ----
    float cw0 = 0.f, cw1 = 0.f, cw2 = 0.f, cw3 = 0.f, cw4 = 0.f, cw5 = 0.f, bsc = 0.f;
    if (lane == 0) {
        const float* wc = Ws + c * 134;
        cw0 = wc[0]; cw1 = wc[1]; cw2 = wc[2];
        cw3 = wc[3]; cw4 = wc[4]; cw5 = wc[5];
        bsc = bs[c];
    }
    const float* pw = Ws + c * 134 + 6;
    float s = pw[lane] * v0 + pw[lane + 32] * v1
            + pw[lane + 64] * v2 + pw[lane + 96] * v3;
    s = warp_sum(s);
    if (lane == 0) {
        float bias = bsc + s;
        float A = cw0 * sK[0] + cw1 * sK[3] + cw2 * sK[6];
        float B = cw0 * sK[1] + cw1 * sK[4] + cw2 * sK[7];
        float C = cw0 * sK[2] + cw1 * sK[5] + cw2 * sK[8]
                + A * soff[0] + B * soff[1];
        float4* dst = reinterpret_cast<float4*>(sP + warp * 16);
        dst[0] = make_float4(A,   A,   B,   B);
        dst[1] = make_float4(C,   C,   cw3, cw3);
        dst[2] = make_float4(cw4, cw4, cw5, cw5);
        dst[3] = make_float4(bias, bias, 0.0f, 0.0f);
    }
    __syncthreads();

    // ---- pixel phase (R14 verbatim: 1 quad/thread, 8 channels) ----
    const int q   = (blk * 256 + t) & 16383;
    const int p0  = q * 4;
    const int r   = p0 >> 8;
    const int cc0 = p0 & 255;

    const int x1 = sbox[0], y1 = sbox[1], x2 = sbox[2], y2 = sbox[3];

    float4 dz = *reinterpret_cast<const float4*>(depth + p0);
    const float4* rp = reinterpret_cast<const float4*>(rgb + (size_t)p0 * 3);
    float4 q0 = rp[0], q1 = rp[1], q2 = rp[2];

    u64 u01 = pair2((float)cc0,       (float)(cc0 + 1));
    u64 u23 = pair2((float)(cc0 + 2), (float)(cc0 + 3));
    u64 v2p = pk2((float)r);
    u64 z01 = pair2(dz.x, dz.y), z23 = pair2(dz.z, dz.w);
    u64 r01 = pair2(q0.x, q0.w), r23 = pair2(q1.z, q2.y);
    u64 g01 = pair2(q0.y, q1.x), g23 = pair2(q1.w, q2.z);
    u64 b01 = pair2(q0.z, q1.y), b23 = pair2(q2.x, q2.w);

    const bool rowin = (r >= x1) && (r < x2);
    bool in0 = rowin && (cc0     >= y1) && (cc0     < y2);
    bool in1 = rowin && (cc0 + 1 >= y1) && (cc0 + 1 < y2);
    bool in2 = rowin && (cc0 + 2 >= y1) && (cc0 + 2 < y2);
    bool in3 = rowin && (cc0 + 3 >= y1) && (cc0 + 3 < y2);
    const bool allin = in0 & in1 & in2 & in3;
    u64 m01 = 0, m23 = 0;
    if (!allin) {
        m01 = (in0 ? 0xFFFFFFFFull : 0ull) | (in1 ? 0xFFFFFFFF00000000ull : 0ull);
        m23 = (in2 ? 0xFFFFFFFFull : 0ull) | (in3 ? 0xFFFFFFFF00000000ull : 0ull);
    }

    float* outbase = out + (size_t)cbase * HWPIX + p0;

    #pragma unroll
    for (int cn = 0; cn < 8; cn++) {
        const ulonglong2* cf = reinterpret_cast<const ulonglong2*>(sP + cn * 16);
        ulonglong2 c0 = cf[0];   // A, B
        ulonglong2 c1 = cf[1];   // C, w3
        ulonglong2 c2 = cf[2];   // w4, w5
        ulonglong2 c3 = cf[3];   // bias, 0

        u64 base = fma2(c0.y, v2p, c1.x);         // B*v + C''
        u64 t01  = fma2(c0.x, u01, base);
        u64 t23  = fma2(c0.x, u23, base);

        u64 d01 = fma2(c1.y, r01, fma2(c2.x, g01, fma2(c2.y, b01, c3.x)));
        u64 d23 = fma2(c1.y, r23, fma2(c2.x, g23, fma2(c2.y, b23, c3.x)));

        u64 s01 = fma2(z01, t01, d01);
        u64 s23 = fma2(z23, t23, d23);
        if (!allin) { s01 &= m01; s23 &= m23; }

        ulonglong2 o; o.x = s01; o.y = s23;
        *reinterpret_cast<ulonglong2*>(outbase + (size_t)cn * HWPIX) = o;
    }
}

extern "C" void kernel_launch(void* const* d_in, const int* in_sizes, int n_in,
                              void* d_out, int out_size)
{
    const float* rgb   = (const float*)d_in[0];
    const float* depth = (const float*)d_in[1];
    const float* intr  = (const float*)d_in[2];
    const int*   box   = (const int*)  d_in[3];
    const float* be5   = (const float*)d_in[23];
    const float* Wd3   = (const float*)d_in[24];
    const float* bd3   = (const float*)d_in[25];
    const float* Ws    = (const float*)d_in[26];
    const float* bs    = (const float*)d_in[27];
    float* out = (float*)d_out;

    frustum_all_kernel<<<640, 256>>>(rgb, depth, intr, box,
                                     be5, Wd3, bd3, Ws, bs, out);
}